// round 16
// baseline (speedup 1.0000x reference)
#include <cuda_runtime.h>
#include <cuda_fp16.h>
#include <cstdint>

typedef unsigned int u32;

#define BB   512
#define TT   1024
#define TM1  1023
#define II   32
#define EE   32
#define HH   256
#define KIN  64

#define NCTA 64
#define BPB  8
#define NTH  512     // 16 warps

// per-warp streams: warps 0-7: 156 tiles; warps 8-15: 160 (incl. 4 GY tiles)
#define NTILE_TOT (8*156 + 8*160)   // 2528

#define XSTR 584
#define HSTR 264

#define RES_T 21                    // SMEM-resident tiles per warp (head 12 + GC kt0-2)
#define RES_B (RES_T * 512)         // 10752 B per warp
#define DSMEM (16 * RES_B)          // 172032 B dynamic

__device__ __align__(1024) __half SCHED[NTILE_TOT * 256];

// ---- prep: identical to R13/R14 ----
__global__ void prep_kernel(const float* __restrict__ wih0, const float* __restrict__ whh0,
                            const float* __restrict__ wih1, const float* __restrict__ whh1,
                            const float* __restrict__ wout)
{
    int idx = blockIdx.x * blockDim.x + threadIdx.x;
    if (idx >= NTILE_TOT * 256) return;
    const int j    = idx & 7;
    const int lane = (idx >> 3) & 31;
    const int tile = idx >> 8;

    int w, r;
    if (tile < 8 * 156) { w = tile / 156; r = tile % 156; }
    else { int t2 = tile - 8 * 156; w = 8 + t2 / 160; r = t2 % 160; }

    const int tq = lane & 3;
    const int il = (lane >> 2) + 8 * ((j >> 1) & 1);
    const int kl = tq * 2 + (j & 1) + 8 * (j >> 2);

    float v;
    if (r < 12) {              // head: W_ih0 x-part, kt0-3 {r,z,i}
        const int kt = r / 3, kind = r % 3;
        v = wih0[(kind * 256 + 16 * w + il) * KIN + kt * 16 + kl];
    } else if (r < 60) {       // GC: W_ih1 {r,z,i}
        const int rr = r - 12, kt = rr / 3, kind = rr % 3;
        v = wih1[(kind * 256 + 16 * w + il) * HH + kt * 16 + kl];
    } else if (r < 108) {      // G0h: W_hh0 {r,z,h}
        const int rr = r - 60, kt = rr / 3, kind = rr % 3;
        v = whh0[(kind * 256 + 16 * w + il) * HH + kt * 16 + kl];
    } else if (r < 156) {      // GB: W_hh1 {r,z,h}
        const int rr = r - 108, kt = rr / 3, kind = rr % 3;
        v = whh1[(kind * 256 + 16 * w + il) * HH + kt * 16 + kl];
    } else {                   // GY (warps 8-15)
        const int local = r - 156;
        const int kt = 2 * (w - 8) + (local >> 1);
        const int mt = local & 1;
        v = wout[(16 * mt + il) * HH + kt * 16 + kl];
    }
    SCHED[tile * 256 + lane * 8 + j] = __float2half_rn(v);
}

__device__ __forceinline__ float tanha(float x) {
    float y; asm("tanh.approx.f32 %0, %1;" : "=f"(y) : "f"(x)); return y;
}
__device__ __forceinline__ float siga(float x) {
    return fmaf(tanha(0.5f * x), 0.5f, 0.5f);
}
__device__ __forceinline__ void hmma(float* c, uint4 a, u32 b0, u32 b1) {
    asm volatile("mma.sync.aligned.m16n8k16.row.col.f32.f16.f16.f32 "
                 "{%0,%1,%2,%3}, {%4,%5,%6,%7}, {%8,%9}, {%0,%1,%2,%3};"
                 : "+f"(c[0]), "+f"(c[1]), "+f"(c[2]), "+f"(c[3])
                 : "r"(a.x), "r"(a.y), "r"(a.z), "r"(a.w), "r"(b0), "r"(b1));
}
__device__ __forceinline__ uint4 ldgnc(const __half* p) {
    uint4 v;
    asm("ld.global.nc.v4.u32 {%0,%1,%2,%3}, [%4];"
        : "=r"(v.x), "=r"(v.y), "=r"(v.z), "=r"(v.w) : "l"(p));
    return v;
}
#define BARX(id, cnt) asm volatile("bar.sync %0, %1;" :: "r"(id), "r"(cnt) : "memory")

__global__ void __launch_bounds__(NTH, 1)
arrnn_kernel(const float* __restrict__ X,
             const float* __restrict__ ENC,
             const int*   __restrict__ MASK,
             const float* __restrict__ bih0, const float* __restrict__ bhh0,
             const float* __restrict__ bih1, const float* __restrict__ bhh1,
             const float* __restrict__ bout,
             float* __restrict__ outseq, float* __restrict__ outh1,
             int write_h1)
{
    __shared__ __align__(16) __half XB[BPB * XSTR];
    __shared__ __align__(16) __half H1B[BPB * HSTR];
    __shared__ __align__(16) float  bsm[8 * 256];
    __shared__ __align__(16) float4 PY[16][32];
    extern __shared__ __align__(16) char WRES[];   // 16 warps x 21 tiles x 512B

    const int tid  = threadIdx.x;
    const int wid  = tid >> 5;
    const int lane = tid & 31;
    const int g    = lane >> 2;
    const int tq   = lane & 3;
    const int b0g  = blockIdx.x * BPB;

    const int u1 = 16 * wid + g;
    const int u2 = u1 + 8;

    for (int i = tid; i < 8 * 256; i += NTH) {
        const int k = i >> 8, u = i & 255;
        float v;
        switch (k) {
            case 0: v = bih0[u] + bhh0[u]; break;
            case 1: v = bih0[256 + u] + bhh0[256 + u]; break;
            case 2: v = bih0[512 + u]; break;
            case 3: v = bhh0[512 + u]; break;
            case 4: v = bih1[u] + bhh1[u]; break;
            case 5: v = bih1[256 + u] + bhh1[256 + u]; break;
            case 6: v = bih1[512 + u]; break;
            default: v = bhh1[512 + u]; break;
        }
        bsm[i] = v;
    }
    const float bya = (wid < 2) ? bout[16 * wid + g] : 0.0f;
    const float byb = (wid < 2) ? bout[16 * wid + g + 8] : 0.0f;

    float h0[4] = {0.f, 0.f, 0.f, 0.f};
    float h1[4] = {0.f, 0.f, 0.f, 0.f};
    float Cr[4] = {0,0,0,0}, Cz[4] = {0,0,0,0}, Ch[4] = {0,0,0,0};
    float Dr[4] = {0,0,0,0}, Dz[4] = {0,0,0,0}, Dh[4] = {0,0,0,0};

    for (int i = tid; i < BPB * 512; i += NTH)
        XB[(i >> 9) * XSTR + 64 + (i & 511)] = __float2half_rn(0.f);
    for (int i = tid; i < BPB * HSTR; i += NTH) H1B[i] = __float2half_rn(0.f);
    for (int i = tid; i < BPB * KIN; i += NTH) {
        const int b = i >> 6, k = i & 63;
        const int gb = b0g + b;
        const float v = (k < II) ? X[((size_t)gb * TT) * II + k]
                                 : ENC[((size_t)gb * TT + 1) * EE + (k - II)];
        XB[b * XSTR + k] = __float2half_rn(v);
    }

    const int base_t = (wid < 8) ? wid * 156 : 8 * 156 + (wid - 8) * 160;
    const __half* tpw = SCHED + (size_t)base_t * 256 + lane * 8;
    const __half* gyp = tpw + 156 * 256;     // valid for wid>=8 only

    // stage resident tiles (0..20 of each warp's stream) into SMEM once
    char* rbase = WRES + wid * RES_B + lane * 16;
#pragma unroll
    for (int i = 0; i < RES_T; ++i)
        *(uint4*)(rbase + i * 512) = ldgnc(tpw + i * 256);
    __syncthreads();

    const __half* tpw_ldg = tpw + RES_T * 256;   // LDG stream starts at tile 21

    for (int t = 0; t < TM1; ++t) {
        const int bi = t & 1;
        const __half* xr = XB + g * XSTR;

        // ================= HEAD: x-part of G0 (kt0-3, all SMEM-resident) =======
        float Ci[4] = {0.f,0.f,0.f,0.f};
#pragma unroll
        for (int kt = 0; kt < 4; ++kt) {
            const u32 b0 = *(const u32*)(xr + kt * 16 + 2 * tq);
            const u32 b1 = *(const u32*)(xr + kt * 16 + 8 + 2 * tq);
            const uint4 ar = *(const uint4*)(rbase + (3 * kt    ) * 512);
            const uint4 az = *(const uint4*)(rbase + (3 * kt + 1) * 512);
            const uint4 ai = *(const uint4*)(rbase + (3 * kt + 2) * 512);
            hmma(Cr, ar, b0, b1); hmma(Cz, az, b0, b1); hmma(Ci, ai, b0, b1);
        }

        // ---- epi0: h0(t) -> XB buf bi ----
        {
            const float br_a = bsm[u1],       br_b = bsm[u2];
            const float bz_a = bsm[256 + u1], bz_b = bsm[256 + u2];
            const float bi_a = bsm[512 + u1], bi_b = bsm[512 + u2];
            const float bn_a = bsm[768 + u1], bn_b = bsm[768 + u2];
#pragma unroll
            for (int p = 0; p < 4; ++p) {
                const bool a = (p < 2);
                const float rr = siga(Cr[p] + (a ? br_a : br_b));
                const float zz = siga(Cz[p] + (a ? bz_a : bz_b));
                const float nn = tanha(Ci[p] + (a ? bi_a : bi_b) + rr * (Ch[p] + (a ? bn_a : bn_b)));
                h0[p] = (1.0f - zz) * nn + zz * h0[p];
                XB[(2 * tq + (p & 1)) * XSTR + 64 + bi * 256 + (a ? u1 : u2)]
                    = __float2half_rn(h0[p]);
            }
        }
        __syncthreads();   // BAR-A: h0(t) published

        // ================= GC: Wih1 x h0(t), 16kt =================
        const __half* tp = tpw_ldg;
        float Di[4] = {0.f,0.f,0.f,0.f};
        {
            const __half* hb = XB + g * XSTR + 64 + bi * 256;
#pragma unroll
            for (int kt = 0; kt < 3; ++kt) {   // tiles 12-20 (SMEM-resident)
                const u32 b0 = *(const u32*)(hb + kt * 16 + 2 * tq);
                const u32 b1 = *(const u32*)(hb + kt * 16 + 8 + 2 * tq);
                const uint4 ar = *(const uint4*)(rbase + (12 + 3 * kt    ) * 512);
                const uint4 az = *(const uint4*)(rbase + (12 + 3 * kt + 1) * 512);
                const uint4 ai = *(const uint4*)(rbase + (12 + 3 * kt + 2) * 512);
                hmma(Dr, ar, b0, b1); hmma(Dz, az, b0, b1); hmma(Di, ai, b0, b1);
            }
#pragma unroll 4
            for (int kt = 3; kt < 16; ++kt) {  // tiles 21-59 (stream)
                const u32 b0 = *(const u32*)(hb + kt * 16 + 2 * tq);
                const u32 b1 = *(const u32*)(hb + kt * 16 + 8 + 2 * tq);
                uint4 ar = ldgnc(tp); tp += 256;
                uint4 az = ldgnc(tp); tp += 256;
                uint4 ai = ldgnc(tp); tp += 256;
                hmma(Dr, ar, b0, b1); hmma(Dz, az, b0, b1); hmma(Di, ai, b0, b1);
            }
        }

        // ---- epi1: h1(t) -> H1B ----
        {
            const float br_a = bsm[1024 + u1], br_b = bsm[1024 + u2];
            const float bz_a = bsm[1280 + u1], bz_b = bsm[1280 + u2];
            const float bi_a = bsm[1536 + u1], bi_b = bsm[1536 + u2];
            const float bn_a = bsm[1792 + u1], bn_b = bsm[1792 + u2];
#pragma unroll
            for (int p = 0; p < 4; ++p) {
                const bool a = (p < 2);
                const float rr = siga(Dr[p] + (a ? br_a : br_b));
                const float zz = siga(Dz[p] + (a ? bz_a : bz_b));
                const float nn = tanha(Di[p] + (a ? bi_a : bi_b) + rr * (Dh[p] + (a ? bn_a : bn_b)));
                h1[p] = (1.0f - zz) * nn + zz * h1[p];
                H1B[(2 * tq + (p & 1)) * HSTR + (a ? u1 : u2)] = __float2half_rn(h1[p]);
            }
        }

        // prefetch tail kt0 (tiles 60-62) + warps 0,1: next-step mask/X
        uint4 pt0 = ldgnc(tpw + 60 * 256);
        uint4 pt1 = ldgnc(tpw + 61 * 256);
        uint4 pt2 = ldgnc(tpw + 62 * 256);
        tp += 3 * 256;     // skip prefetched tiles 60-62 in the stream
        int kp0 = 0, kp1 = 0;
        float xpre[4];
        if (wid < 2) {
            kp0 = MASK[(b0g + 2 * tq) * TT + (t + 1)];
            kp1 = MASK[(b0g + 2 * tq + 1) * TT + (t + 1)];
#pragma unroll
            for (int p = 0; p < 4; ++p) {
                const int i = 16 * wid + g + ((p < 2) ? 0 : 8);
                const int b = 2 * tq + (p & 1);
                xpre[p] = X[((size_t)(b0g + b) * TT + (t + 1)) * II + i];
            }
        }
        __syncthreads();   // BAR-B: h1(t) published

        // ================= TAIL =================
        if (wid >= 2 && wid < 10) {        // enc(t+2) for the next head
            const int i2 = tid - 64;
            const int b = i2 >> 5, k = i2 & 31;
            const int eidx = (t + 2 < TT) ? (t + 2) : (TT - 1);
            XB[b * XSTR + 32 + k] =
                __float2half_rn(ENC[((size_t)(b0g + b) * TT + eidx) * EE + k]);
        }
        if (wid >= 8) {                    // GY partials
            float Ym[8] = {0,0,0,0,0,0,0,0};
            const __half* hr = H1B + g * HSTR;
            const int kbase = 2 * (wid - 8);
#pragma unroll
            for (int l = 0; l < 4; ++l) {
                const int kt = kbase + (l >> 1);
                uint4 ay = ldgnc(gyp + l * 256);
                const u32 b0 = *(const u32*)(hr + kt * 16 + 2 * tq);
                const u32 b1 = *(const u32*)(hr + kt * 16 + 8 + 2 * tq);
                hmma(Ym + 4 * (l & 1), ay, b0, b1);
            }
            PY[(wid - 8) * 2 + 0][lane] = make_float4(Ym[0], Ym[1], Ym[2], Ym[3]);
            PY[(wid - 8) * 2 + 1][lane] = make_float4(Ym[4], Ym[5], Ym[6], Ym[7]);
            asm volatile("bar.arrive 7, 320;" ::: "memory");
        }
        if (wid < 2) {                     // GY reduce + y/x write
            asm volatile("bar.sync 7, 320;" ::: "memory");
            float Y0 = 0.f, Y1 = 0.f, Y2 = 0.f, Y3 = 0.f;
#pragma unroll
            for (int w = 0; w < 8; ++w) {
                const float4 v = PY[w * 2 + wid][lane];
                Y0 += v.x; Y1 += v.y; Y2 += v.z; Y3 += v.w;
            }
            float Y[4] = {Y0, Y1, Y2, Y3};
#pragma unroll
            for (int p = 0; p < 4; ++p) {
                const bool a = (p < 2);
                const int i = 16 * wid + g + (a ? 0 : 8);
                const int b = 2 * tq + (p & 1);
                const float y = Y[p] + (a ? bya : byb);
                outseq[((size_t)(b0g + b) * TM1 + t) * II + i] = y;
                const bool keep = ((p & 1) ? kp1 : kp0) != 0;
                XB[b * XSTR + i] = __float2half_rn(keep ? xpre[p] : y);
            }
        }

        // ---- G0h(t+1): Whh0 x h0(t), carry into Cr,Cz,Ch ----
#pragma unroll
        for (int p = 0; p < 4; ++p) { Cr[p] = 0.f; Cz[p] = 0.f; Ch[p] = 0.f; }
        {
            const __half* hb = XB + g * XSTR + 64 + bi * 256;
            {
                const u32 b0 = *(const u32*)(hb + 2 * tq);
                const u32 b1 = *(const u32*)(hb + 8 + 2 * tq);
                hmma(Cr, pt0, b0, b1); hmma(Cz, pt1, b0, b1); hmma(Ch, pt2, b0, b1);
            }
#pragma unroll 4
            for (int kt = 1; kt < 16; ++kt) {
                const u32 b0 = *(const u32*)(hb + kt * 16 + 2 * tq);
                const u32 b1 = *(const u32*)(hb + kt * 16 + 8 + 2 * tq);
                uint4 ar = ldgnc(tp); tp += 256;
                uint4 az = ldgnc(tp); tp += 256;
                uint4 ah = ldgnc(tp); tp += 256;
                hmma(Cr, ar, b0, b1); hmma(Cz, az, b0, b1); hmma(Ch, ah, b0, b1);
            }
        }
        // ---- GB(t+1): Whh1 x h1(t), carry into Dr,Dz,Dh ----
#pragma unroll
        for (int p = 0; p < 4; ++p) { Dr[p] = 0.f; Dz[p] = 0.f; Dh[p] = 0.f; }
        {
            const __half* hr = H1B + g * HSTR;
#pragma unroll 4
            for (int kt = 0; kt < 16; ++kt) {
                const u32 b0 = *(const u32*)(hr + kt * 16 + 2 * tq);
                const u32 b1 = *(const u32*)(hr + kt * 16 + 8 + 2 * tq);
                uint4 ar = ldgnc(tp); tp += 256;
                uint4 az = ldgnc(tp); tp += 256;
                uint4 ah = ldgnc(tp); tp += 256;
                hmma(Dr, ar, b0, b1); hmma(Dz, az, b0, b1); hmma(Dh, ah, b0, b1);
            }
        }
        __syncthreads();   // BAR-C: x(t+1)/enc published
    }

    if (write_h1) {
#pragma unroll
        for (int p = 0; p < 4; ++p) {
            const int b = b0g + 2 * tq + (p & 1);
            const int u = (p < 2) ? u1 : u2;
            outh1[(size_t)b * HH + u] = h1[p];
        }
    }
}

extern "C" void kernel_launch(void* const* d_in, const int* in_sizes, int n_in,
                              void* d_out, int out_size) {
    const float* X    = (const float*)d_in[0];
    const float* ENC  = (const float*)d_in[1];
    const int*   MASK = (const int*)d_in[2];
    const float* wih0 = (const float*)d_in[3];
    const float* whh0 = (const float*)d_in[4];
    const float* bih0 = (const float*)d_in[5];
    const float* bhh0 = (const float*)d_in[6];
    const float* wih1 = (const float*)d_in[7];
    const float* whh1 = (const float*)d_in[8];
    const float* bih1 = (const float*)d_in[9];
    const float* bhh1 = (const float*)d_in[10];
    const float* wout = (const float*)d_in[11];
    const float* bout = (const float*)d_in[12];

    float* outseq = (float*)d_out;
    const int seqsz = BB * TM1 * II;
    float* outh1  = outseq + seqsz;
    const int write_h1 = (out_size >= seqsz + BB * HH) ? 1 : 0;

    prep_kernel<<<(NTILE_TOT * 256 + 255) / 256, 256>>>(wih0, whh0, wih1, whh1, wout);

    cudaFuncSetAttribute(arrnn_kernel, cudaFuncAttributeMaxDynamicSharedMemorySize, DSMEM);
    arrnn_kernel<<<NCTA, NTH, DSMEM>>>(X, ENC, MASK,
                                       bih0, bhh0, bih1, bhh1, bout,
                                       outseq, outh1, write_h1);
}

// round 17
// speedup vs baseline: 1.2801x; 1.2801x over previous
#include <cuda_runtime.h>
#include <cuda_fp16.h>
#include <cstdint>

typedef unsigned int u32;

#define BB   512
#define TT   1024
#define TM1  1023
#define II   32
#define EE   32
#define HH   256
#define KIN  64

#define NCTA 64
#define BPB  8
#define NTH  512     // 16 warps

// per-warp streams: warps 0-7: 156 tiles; warps 8-15: 160 (incl. 4 GY tiles)
#define NTILE_TOT (8*156 + 8*160)   // 2528

// XB row: [x(64) | h0_buf0(256) | h0_buf1(256)] pad-> 584 halfs
#define XSTR 584
#define HSTR 264

__device__ __align__(1024) __half SCHED[NTILE_TOT * 256];

// ---- prep: consumption order = head(x-part 12) | GC(48) | G0h(48) | GB(48) | [GY(4) w>=8]
__global__ void prep_kernel(const float* __restrict__ wih0, const float* __restrict__ whh0,
                            const float* __restrict__ wih1, const float* __restrict__ whh1,
                            const float* __restrict__ wout)
{
    int idx = blockIdx.x * blockDim.x + threadIdx.x;
    if (idx >= NTILE_TOT * 256) return;
    const int j    = idx & 7;
    const int lane = (idx >> 3) & 31;
    const int tile = idx >> 8;

    int w, r;
    if (tile < 8 * 156) { w = tile / 156; r = tile % 156; }
    else { int t2 = tile - 8 * 156; w = 8 + t2 / 160; r = t2 % 160; }

    const int tq = lane & 3;
    const int il = (lane >> 2) + 8 * ((j >> 1) & 1);
    const int kl = tq * 2 + (j & 1) + 8 * (j >> 2);

    float v;
    if (r < 12) {              // head: W_ih0 x-part, kt0-3 {r,z,i}
        const int kt = r / 3, kind = r % 3;
        v = wih0[(kind * 256 + 16 * w + il) * KIN + kt * 16 + kl];
    } else if (r < 60) {       // GC: W_ih1 {r,z,i}
        const int rr = r - 12, kt = rr / 3, kind = rr % 3;
        v = wih1[(kind * 256 + 16 * w + il) * HH + kt * 16 + kl];
    } else if (r < 108) {      // G0h: W_hh0 {r,z,h}
        const int rr = r - 60, kt = rr / 3, kind = rr % 3;
        v = whh0[(kind * 256 + 16 * w + il) * HH + kt * 16 + kl];
    } else if (r < 156) {      // GB: W_hh1 {r,z,h}
        const int rr = r - 108, kt = rr / 3, kind = rr % 3;
        v = whh1[(kind * 256 + 16 * w + il) * HH + kt * 16 + kl];
    } else {                   // GY (warps 8-15): kt = 2*(w-8)+(local>>1), mtile = local&1
        const int local = r - 156;
        const int kt = 2 * (w - 8) + (local >> 1);
        const int mt = local & 1;
        v = wout[(16 * mt + il) * HH + kt * 16 + kl];
    }
    SCHED[tile * 256 + lane * 8 + j] = __float2half_rn(v);
}

__device__ __forceinline__ float tanha(float x) {
    float y; asm("tanh.approx.f32 %0, %1;" : "=f"(y) : "f"(x)); return y;
}
__device__ __forceinline__ float siga(float x) {
    return fmaf(tanha(0.5f * x), 0.5f, 0.5f);
}
__device__ __forceinline__ void hmma(float* c, uint4 a, u32 b0, u32 b1) {
    asm volatile("mma.sync.aligned.m16n8k16.row.col.f32.f16.f16.f32 "
                 "{%0,%1,%2,%3}, {%4,%5,%6,%7}, {%8,%9}, {%0,%1,%2,%3};"
                 : "+f"(c[0]), "+f"(c[1]), "+f"(c[2]), "+f"(c[3])
                 : "r"(a.x), "r"(a.y), "r"(a.z), "r"(a.w), "r"(b0), "r"(b1));
}

__global__ void __launch_bounds__(NTH, 1)
arrnn_kernel(const float* __restrict__ X,
             const float* __restrict__ ENC,
             const int*   __restrict__ MASK,
             const float* __restrict__ bih0, const float* __restrict__ bhh0,
             const float* __restrict__ bih1, const float* __restrict__ bhh1,
             const float* __restrict__ bout,
             float* __restrict__ outseq, float* __restrict__ outh1,
             int write_h1)
{
    __shared__ __align__(16) __half XB[BPB * XSTR];
    __shared__ __align__(16) __half H1B[BPB * HSTR];
    __shared__ __align__(16) float  bsm[8 * 256];
    __shared__ __align__(16) float4 PY[16][32];    // GY partials [w8*2+mtile][lane]

    const int tid  = threadIdx.x;
    const int wid  = tid >> 5;
    const int lane = tid & 31;
    const int g    = lane >> 2;
    const int tq   = lane & 3;
    const int b0g  = blockIdx.x * BPB;

    const int u1 = 16 * wid + g;
    const int u2 = u1 + 8;

    // biases in SMEM
    for (int i = tid; i < 8 * 256; i += NTH) {
        const int k = i >> 8, u = i & 255;
        float v;
        switch (k) {
            case 0: v = bih0[u] + bhh0[u]; break;
            case 1: v = bih0[256 + u] + bhh0[256 + u]; break;
            case 2: v = bih0[512 + u]; break;
            case 3: v = bhh0[512 + u]; break;
            case 4: v = bih1[u] + bhh1[u]; break;
            case 5: v = bih1[256 + u] + bhh1[256 + u]; break;
            case 6: v = bih1[512 + u]; break;
            default: v = bhh1[512 + u]; break;
        }
        bsm[i] = v;
    }
    const float bya = (wid < 2) ? bout[16 * wid + g] : 0.0f;
    const float byb = (wid < 2) ? bout[16 * wid + g + 8] : 0.0f;

    float h0[4] = {0.f, 0.f, 0.f, 0.f};
    float h1[4] = {0.f, 0.f, 0.f, 0.f};

    // carry accumulators (h-parts of next step), zero = correct for t=0
    float Cr[4] = {0,0,0,0}, Cz[4] = {0,0,0,0}, Ch[4] = {0,0,0,0};
    float Dr[4] = {0,0,0,0}, Dz[4] = {0,0,0,0}, Dh[4] = {0,0,0,0};

    // init XB / H1B, build x(0)|enc(1)
    for (int i = tid; i < BPB * 512; i += NTH)
        XB[(i >> 9) * XSTR + 64 + (i & 511)] = __float2half_rn(0.f);
    for (int i = tid; i < BPB * HSTR; i += NTH) H1B[i] = __float2half_rn(0.f);
    for (int i = tid; i < BPB * KIN; i += NTH) {
        const int b = i >> 6, k = i & 63;
        const int gb = b0g + b;
        const float v = (k < II) ? X[((size_t)gb * TT) * II + k]
                                 : ENC[((size_t)gb * TT + 1) * EE + (k - II)];
        XB[b * XSTR + k] = __float2half_rn(v);
    }
    __syncthreads();

    const int base_t = (wid < 8) ? wid * 156 : 8 * 156 + (wid - 8) * 160;
    const __half* tpw = SCHED + (size_t)base_t * 256 + lane * 8;
    const __half* gyp = tpw + 156 * 256;     // valid for wid>=8 only

    // prefetch head kt0 (tiles 0-2)
    uint4 pg0 = *(const uint4*)(tpw);
    uint4 pg1 = *(const uint4*)(tpw + 256);
    uint4 pg2 = *(const uint4*)(tpw + 512);

    for (int t = 0; t < TM1; ++t) {
        const int bi = t & 1;                 // h0 buffer for this step
        const __half* xr = XB + g * XSTR;

        // ================= HEAD: x-part of G0 (kt0-3) =================
        float Ci[4] = {0.f,0.f,0.f,0.f};
        {
            const u32 b0 = *(const u32*)(xr + 2 * tq);
            const u32 b1 = *(const u32*)(xr + 8 + 2 * tq);
            hmma(Cr, pg0, b0, b1); hmma(Cz, pg1, b0, b1); hmma(Ci, pg2, b0, b1);
        }
        const __half* tp = tpw + 3 * 256;
#pragma unroll
        for (int kt = 1; kt < 4; ++kt) {
            const u32 b0 = *(const u32*)(xr + kt * 16 + 2 * tq);
            const u32 b1 = *(const u32*)(xr + kt * 16 + 8 + 2 * tq);
            uint4 ar = *(const uint4*)tp; tp += 256;
            uint4 az = *(const uint4*)tp; tp += 256;
            uint4 ai = *(const uint4*)tp; tp += 256;
            hmma(Cr, ar, b0, b1); hmma(Cz, az, b0, b1); hmma(Ci, ai, b0, b1);
        }
        // prefetch GC kt0 (tiles 12-14)
        uint4 pc0 = *(const uint4*)(tp);
        uint4 pc1 = *(const uint4*)(tp + 256);
        uint4 pc2 = *(const uint4*)(tp + 512);
        tp += 3 * 256;

        // ---- epi0: h0(t) -> XB buf bi ----
        {
            const float br_a = bsm[u1],       br_b = bsm[u2];
            const float bz_a = bsm[256 + u1], bz_b = bsm[256 + u2];
            const float bi_a = bsm[512 + u1], bi_b = bsm[512 + u2];
            const float bn_a = bsm[768 + u1], bn_b = bsm[768 + u2];
#pragma unroll
            for (int p = 0; p < 4; ++p) {
                const bool a = (p < 2);
                const float rr = siga(Cr[p] + (a ? br_a : br_b));
                const float zz = siga(Cz[p] + (a ? bz_a : bz_b));
                const float nn = tanha(Ci[p] + (a ? bi_a : bi_b) + rr * (Ch[p] + (a ? bn_a : bn_b)));
                h0[p] = (1.0f - zz) * nn + zz * h0[p];
                XB[(2 * tq + (p & 1)) * XSTR + 64 + bi * 256 + (a ? u1 : u2)]
                    = __float2half_rn(h0[p]);
            }
        }
        __syncthreads();   // BAR-A: h0(t) published

        // ================= GC: Wih1 x h0(t), 16kt =================
        float Di[4] = {0.f,0.f,0.f,0.f};
        {
            const __half* hb = XB + g * XSTR + 64 + bi * 256;
            {
                const u32 b0 = *(const u32*)(hb + 2 * tq);
                const u32 b1 = *(const u32*)(hb + 8 + 2 * tq);
                hmma(Dr, pc0, b0, b1); hmma(Dz, pc1, b0, b1); hmma(Di, pc2, b0, b1);
            }
#pragma unroll 4
            for (int kt = 1; kt < 16; ++kt) {
                const u32 b0 = *(const u32*)(hb + kt * 16 + 2 * tq);
                const u32 b1 = *(const u32*)(hb + kt * 16 + 8 + 2 * tq);
                uint4 ar = *(const uint4*)tp; tp += 256;
                uint4 az = *(const uint4*)tp; tp += 256;
                uint4 ai = *(const uint4*)tp; tp += 256;
                hmma(Dr, ar, b0, b1); hmma(Dz, az, b0, b1); hmma(Di, ai, b0, b1);
            }
        }

        // ---- epi1: h1(t) -> H1B ----
        {
            const float br_a = bsm[1024 + u1], br_b = bsm[1024 + u2];
            const float bz_a = bsm[1280 + u1], bz_b = bsm[1280 + u2];
            const float bi_a = bsm[1536 + u1], bi_b = bsm[1536 + u2];
            const float bn_a = bsm[1792 + u1], bn_b = bsm[1792 + u2];
#pragma unroll
            for (int p = 0; p < 4; ++p) {
                const bool a = (p < 2);
                const float rr = siga(Dr[p] + (a ? br_a : br_b));
                const float zz = siga(Dz[p] + (a ? bz_a : bz_b));
                const float nn = tanha(Di[p] + (a ? bi_a : bi_b) + rr * (Dh[p] + (a ? bn_a : bn_b)));
                h1[p] = (1.0f - zz) * nn + zz * h1[p];
                H1B[(2 * tq + (p & 1)) * HSTR + (a ? u1 : u2)] = __float2half_rn(h1[p]);
            }
        }

        // prefetch tail kt0 (tiles 60-62) + warps 0,1: next-step mask/X
        pg0 = *(const uint4*)(tpw + 60 * 256);
        pg1 = *(const uint4*)(tpw + 61 * 256);
        pg2 = *(const uint4*)(tpw + 62 * 256);
        tp += 3 * 256;     // stream now points at tile 63 (G0h kt1)
        int kp0 = 0, kp1 = 0;
        float xpre[4];
        if (wid < 2) {
            kp0 = MASK[(b0g + 2 * tq) * TT + (t + 1)];
            kp1 = MASK[(b0g + 2 * tq + 1) * TT + (t + 1)];
#pragma unroll
            for (int p = 0; p < 4; ++p) {
                const int i = 16 * wid + g + ((p < 2) ? 0 : 8);
                const int b = 2 * tq + (p & 1);
                xpre[p] = X[((size_t)(b0g + b) * TT + (t + 1)) * II + i];
            }
        }
        __syncthreads();   // BAR-B: h1(t) published

        // ================= TAIL =================
        // enc(t+2) for the next head (warps 2-9)
        if (wid >= 2 && wid < 10) {
            const int i2 = tid - 64;
            const int b = i2 >> 5, k = i2 & 31;
            const int eidx = (t + 2 < TT) ? (t + 2) : (TT - 1);
            XB[b * XSTR + 32 + k] =
                __float2half_rn(ENC[((size_t)(b0g + b) * TT + eidx) * EE + k]);
        }
        // GY partials (warps 8-15): 2 kt x 2 mtiles each
        if (wid >= 8) {
            float Ym[8] = {0,0,0,0,0,0,0,0};
            const __half* hr = H1B + g * HSTR;
            const int kbase = 2 * (wid - 8);
#pragma unroll
            for (int l = 0; l < 4; ++l) {
                const int kt = kbase + (l >> 1);
                uint4 ay = *(const uint4*)(gyp + l * 256);
                const u32 b0 = *(const u32*)(hr + kt * 16 + 2 * tq);
                const u32 b1 = *(const u32*)(hr + kt * 16 + 8 + 2 * tq);
                hmma(Ym + 4 * (l & 1), ay, b0, b1);
            }
            PY[(wid - 8) * 2 + 0][lane] = make_float4(Ym[0], Ym[1], Ym[2], Ym[3]);
            PY[(wid - 8) * 2 + 1][lane] = make_float4(Ym[4], Ym[5], Ym[6], Ym[7]);
            asm volatile("bar.arrive 7, 320;" ::: "memory");
        }
        // GY reduce + y/x write (warps 0,1)
        if (wid < 2) {
            asm volatile("bar.sync 7, 320;" ::: "memory");
            float Y0 = 0.f, Y1 = 0.f, Y2 = 0.f, Y3 = 0.f;
#pragma unroll
            for (int w = 0; w < 8; ++w) {
                const float4 v = PY[w * 2 + wid][lane];
                Y0 += v.x; Y1 += v.y; Y2 += v.z; Y3 += v.w;
            }
            float Y[4] = {Y0, Y1, Y2, Y3};
#pragma unroll
            for (int p = 0; p < 4; ++p) {
                const bool a = (p < 2);
                const int i = 16 * wid + g + (a ? 0 : 8);
                const int b = 2 * tq + (p & 1);
                const float y = Y[p] + (a ? bya : byb);
                outseq[((size_t)(b0g + b) * TM1 + t) * II + i] = y;
                const bool keep = ((p & 1) ? kp1 : kp0) != 0;
                XB[b * XSTR + i] = __float2half_rn(keep ? xpre[p] : y);
            }
        }

        // ---- FUSED TAIL: G0h(t+1) + GB(t+1), interleaved for 2x MLP ----
#pragma unroll
        for (int p = 0; p < 4; ++p) {
            Cr[p] = 0.f; Cz[p] = 0.f; Ch[p] = 0.f;
            Dr[p] = 0.f; Dz[p] = 0.f; Dh[p] = 0.f;
        }
        {
            const __half* hb  = XB + g * XSTR + 64 + bi * 256;
            const __half* hr  = H1B + g * HSTR;
            const __half* tpB = tpw + 108 * 256;   // GB tile base
            // kt0: G0h from prefetch, GB kt0 from tpB
            {
                const u32 c0 = *(const u32*)(hb + 2 * tq);
                const u32 c1 = *(const u32*)(hb + 8 + 2 * tq);
                const u32 d0 = *(const u32*)(hr + 2 * tq);
                const u32 d1 = *(const u32*)(hr + 8 + 2 * tq);
                uint4 br_ = *(const uint4*)(tpB);
                uint4 bz_ = *(const uint4*)(tpB + 256);
                uint4 bh_ = *(const uint4*)(tpB + 512);
                tpB += 3 * 256;
                hmma(Cr, pg0, c0, c1); hmma(Cz, pg1, c0, c1); hmma(Ch, pg2, c0, c1);
                hmma(Dr, br_, d0, d1); hmma(Dz, bz_, d0, d1); hmma(Dh, bh_, d0, d1);
            }
#pragma unroll 4
            for (int kt = 1; kt < 16; ++kt) {
                const u32 c0 = *(const u32*)(hb + kt * 16 + 2 * tq);
                const u32 c1 = *(const u32*)(hb + kt * 16 + 8 + 2 * tq);
                const u32 d0 = *(const u32*)(hr + kt * 16 + 2 * tq);
                const u32 d1 = *(const u32*)(hr + kt * 16 + 8 + 2 * tq);
                uint4 ar = *(const uint4*)tp;         tp += 256;
                uint4 az = *(const uint4*)tp;         tp += 256;
                uint4 ah = *(const uint4*)tp;         tp += 256;
                uint4 br_ = *(const uint4*)tpB;       tpB += 256;
                uint4 bz_ = *(const uint4*)tpB;       tpB += 256;
                uint4 bh_ = *(const uint4*)tpB;       tpB += 256;
                hmma(Cr, ar, c0, c1); hmma(Cz, az, c0, c1); hmma(Ch, ah, c0, c1);
                hmma(Dr, br_, d0, d1); hmma(Dz, bz_, d0, d1); hmma(Dh, bh_, d0, d1);
            }
        }

        // prefetch next head kt0
        pg0 = *(const uint4*)(tpw);
        pg1 = *(const uint4*)(tpw + 256);
        pg2 = *(const uint4*)(tpw + 512);
        __syncthreads();   // BAR-C: x(t+1)/enc published
    }

    if (write_h1) {
#pragma unroll
        for (int p = 0; p < 4; ++p) {
            const int b = b0g + 2 * tq + (p & 1);
            const int u = (p < 2) ? u1 : u2;
            outh1[(size_t)b * HH + u] = h1[p];
        }
    }
}

extern "C" void kernel_launch(void* const* d_in, const int* in_sizes, int n_in,
                              void* d_out, int out_size) {
    const float* X    = (const float*)d_in[0];
    const float* ENC  = (const float*)d_in[1];
    const int*   MASK = (const int*)d_in[2];
    const float* wih0 = (const float*)d_in[3];
    const float* whh0 = (const float*)d_in[4];
    const float* bih0 = (const float*)d_in[5];
    const float* bhh0 = (const float*)d_in[6];
    const float* wih1 = (const float*)d_in[7];
    const float* whh1 = (const float*)d_in[8];
    const float* bih1 = (const float*)d_in[9];
    const float* bhh1 = (const float*)d_in[10];
    const float* wout = (const float*)d_in[11];
    const float* bout = (const float*)d_in[12];

    float* outseq = (float*)d_out;
    const int seqsz = BB * TM1 * II;
    float* outh1  = outseq + seqsz;
    const int write_h1 = (out_size >= seqsz + BB * HH) ? 1 : 0;

    prep_kernel<<<(NTILE_TOT * 256 + 255) / 256, 256>>>(wih0, whh0, wih1, whh1, wout);

    arrnn_kernel<<<NCTA, NTH>>>(X, ENC, MASK,
                                bih0, bhh0, bih1, bhh1, bout,
                                outseq, outh1, write_h1);
}